// round 13
// baseline (speedup 1.0000x reference)
#include <cuda_runtime.h>
#include <cuda_fp16.h>
#include <cstdint>

#define TPB     512
#define NB      128
#define SEQLEN  8194
#define NL      2048
#define DD      128
#define NT      128
#define NTILES  16
#define WSTR    272      // bytes per row (136 fp16) for W and H tiles

// shared memory layout (bytes)
#define OFF_WHI   0        // 128*272 = 34816
#define OFF_H     34816    // 2 parities x 34816 (H fp16)
#define OFF_MSH   104448   // 3*32*33 f32 = 12672
#define OFF_SSEQ  117120   // 8 warps x 4 s x 20 i32 = 2560
#define OFF_VASH  119680   // 128 f32 = 512
#define OFF_EPART 120192   // 2 x 4 x 132 f32 = 4224
#define OFF_CTXP  124416   // 8*128 f32 = 4096
#define OFF_SCAL  128512   // 32 f32 = 128
#define SMEM_BYTES 128640

// named barriers: 1+p = HREADY(512), 3+p = EREADY(512).
// No GDONE barrier: builder iteration T builds buffer p only after it synced
// EREADY(T-2) (inside its iteration T-1 epilogue), and EREADY(T-2) is arrived
// by GEMM warps only after the k-loop on buffer p finished. No MEMBARs: named
// bar arrive/sync pairs carry CTA-scope memory ordering (BAR drains STS).
#define BAR_ARRIVE(id, cnt) asm volatile("bar.arrive %0, %1;" :: "r"(id), "r"(cnt) : "memory")
#define BAR_SYNC(id, cnt)   asm volatile("bar.sync %0, %1;"   :: "r"(id), "r"(cnt) : "memory")

__device__ __forceinline__ uint32_t smem_u32(const void* p) {
    uint32_t a;
    asm("{ .reg .u64 t; cvta.to.shared.u64 t, %1; cvt.u32.u64 %0, t; }" : "=r"(a) : "l"(p));
    return a;
}
__device__ __forceinline__ void ldsm_x4(uint32_t* r, uint32_t a) {
    asm volatile("ldmatrix.sync.aligned.m8n8.x4.shared.b16 {%0,%1,%2,%3}, [%4];"
                 : "=r"(r[0]), "=r"(r[1]), "=r"(r[2]), "=r"(r[3]) : "r"(a));
}
__device__ __forceinline__ void ldsm_x2(uint32_t& r0, uint32_t& r1, uint32_t a) {
    asm volatile("ldmatrix.sync.aligned.m8n8.x2.shared.b16 {%0,%1}, [%2];"
                 : "=r"(r0), "=r"(r1) : "r"(a));
}
__device__ __forceinline__ void mma16816(float* c, const uint32_t* a, uint32_t b0, uint32_t b1) {
    asm volatile("mma.sync.aligned.m16n8k16.row.col.f32.f16.f16.f32 "
                 "{%0,%1,%2,%3}, {%4,%5,%6,%7}, {%8,%9}, {%0,%1,%2,%3};"
                 : "+f"(c[0]), "+f"(c[1]), "+f"(c[2]), "+f"(c[3])
                 : "r"(a[0]), "r"(a[1]), "r"(a[2]), "r"(a[3]), "r"(b0), "r"(b1));
}
// paired tanh via MUFU.TANH on f16x2: returns {tanh(a), tanh(b)}
__device__ __forceinline__ float2 tanh2(float a, float b) {
    uint32_t d2, t2;
    asm("cvt.rn.f16x2.f32 %0, %1, %2;" : "=r"(d2) : "f"(b), "f"(a));  // lo=a, hi=b
    asm("tanh.approx.f16x2 %0, %1;" : "=r"(t2) : "r"(d2));
    __half2 h = *reinterpret_cast<__half2*>(&t2);
    return __half22float2(h);   // x = tanh(a), y = tanh(b)
}

// warp-local softmax (redundant per warp, bit-identical) + online ctx update
__device__ __forceinline__ void builder_epilogue(
    int pp, int bw, int lane, char* smem, const float* epart,
    float& m_run, float& Z_run, float* ctxAcc)
{
    const float* ep = epart + pp * 528;
    float e[4], mloc = -3.4e38f;
    #pragma unroll
    for (int j = 0; j < 4; j++) {
        int n = lane + j * 32;
        e[j] = ep[n] + ep[132 + n] + ep[264 + n] + ep[396 + n];
        mloc = fmaxf(mloc, e[j]);
    }
    #pragma unroll
    for (int off = 16; off; off >>= 1)
        mloc = fmaxf(mloc, __shfl_xor_sync(0xffffffffu, mloc, off));
    float m_new = fmaxf(m_run, mloc);
    float alpha = __expf(m_run - m_new);
    m_run = m_new;
    float w[4], z = 0.0f;
    #pragma unroll
    for (int j = 0; j < 4; j++) { w[j] = __expf(e[j] - m_new); z += w[j]; }
    #pragma unroll
    for (int off = 16; off; off >>= 1)
        z += __shfl_xor_sync(0xffffffffu, z, off);
    Z_run = Z_run * alpha + z;
    // this warp's 16 weights live in w[bw>>1] on lanes (bw&1)*16..+16
    const int jj = bw >> 1;
    float wq = (jj == 0) ? w[0] : (jj == 1) ? w[1] : (jj == 2) ? w[2] : w[3];
    const int srcb = (bw & 1) * 16;
    const char* hb = smem + OFF_H + pp * 34816;
    float t0 = 0.0f, t1 = 0.0f, t2 = 0.0f, t3 = 0.0f;
    #pragma unroll 4
    for (int i = 0; i < 16; i++) {
        float wv = __shfl_sync(0xffffffffu, wq, srcb + i);
        int n = bw * 16 + i;
        uint2 hv = *(const uint2*)(hb + (uint32_t)n * WSTR + (uint32_t)lane * 8u);
        float2 f0 = __half22float2(*(__half2*)&hv.x);
        float2 f1 = __half22float2(*(__half2*)&hv.y);
        t0 += wv * f0.x; t1 += wv * f0.y; t2 += wv * f1.x; t3 += wv * f1.y;
    }
    ctxAcc[0] = ctxAcc[0] * alpha + t0;
    ctxAcc[1] = ctxAcc[1] * alpha + t1;
    ctxAcc[2] = ctxAcc[2] * alpha + t2;
    ctxAcc[3] = ctxAcc[3] * alpha + t3;
}

__global__ void __launch_bounds__(TPB, 1)
dingo_kernel(const int*   __restrict__ seq,
             const float* __restrict__ emb,
             const float* __restrict__ convw,
             const float* __restrict__ convb,
             const float* __restrict__ Wa,
             const float* __restrict__ va,
             float*       __restrict__ out)
{
    extern __shared__ char smem[];
    const uint32_t sb = smem_u32(smem);
    float* Msh   = (float*)(smem + OFF_MSH);   // [3][32][33], bias folded into k=0
    int*   sseq  = (int*)  (smem + OFF_SSEQ);  // per-warp slices [8][4][20]
    float* vash  = (float*)(smem + OFF_VASH);
    float* epart = (float*)(smem + OFF_EPART);
    float* ctxp  = (float*)(smem + OFF_CTXP);
    float* scal  = (float*)(smem + OFF_SCAL);

    const int b    = blockIdx.x;
    const int tid  = threadIdx.x;
    const int wid  = tid >> 5;
    const int lane = tid & 31;
    const int* seqb = seq + b * SEQLEN;

    // ---- setup (all 512): W fp16 row-major [dw][e]; conv-fold tables ----
    for (int i = tid; i < DD * DD; i += TPB) {
        int dw = i >> 7, e = i & 127;
        *(__half*)(smem + OFF_WHI + dw * WSTR + e * 2) = __float2half_rn(Wa[i]);
    }
    for (int i = tid; i < 3 * 32 * 26; i += TPB) {
        int k = i / 832, r = i - k * 832;
        int c = r / 26, tt = r - c * 26;
        float acc = (k == 0) ? convb[c] : 0.0f;
        #pragma unroll
        for (int q = 0; q < 5; q++)
            acc += emb[tt * 5 + q] * convw[(c * 5 + q) * 3 + k];
        Msh[(k * 32 + c) * 33 + tt] = acc;
    }
    if (tid < 128) vash[tid] = va[tid];
    __syncthreads();

    if (tid < 256) {
        // ========= GEMM warps (0-7): m32 x n64, single fp16 term =========
        const int gm = wid & 3, gn = wid >> 2;
        const uint32_t aBase = (uint32_t)(32 * gm + (lane & 15)) * WSTR
                             + (uint32_t)((lane >> 4) & 1) * 16u;
        const uint32_t aHi0 = sb + OFF_WHI + aBase;
        const uint32_t aHi1 = aHi0 + 16u * WSTR;
        const int ll = lane & 15;
        const uint32_t bBase = (uint32_t)(64 * gn + (ll & 7)) * WSTR
                             + (uint32_t)((ll >> 3) & 1) * 16u;
        const int g = lane >> 2, tc = lane & 3;
        const float v00 = vash[32 * gm + g],      v01 = vash[32 * gm + 8 + g];
        const float v10 = vash[32 * gm + 16 + g], v11 = vash[32 * gm + 24 + g];

        for (int tile = 0; tile < NTILES; tile++) {
            const int p = tile & 1;
            BAR_SYNC(1 + p, 512);                  // H(tile) ready
            const uint32_t bH = sb + OFF_H + (uint32_t)p * 34816u + bBase;

            float acc[2][8][4];
            #pragma unroll
            for (int mi = 0; mi < 2; mi++)
                #pragma unroll
                for (int j = 0; j < 8; j++)
                    #pragma unroll
                    for (int q = 0; q < 4; q++) acc[mi][j][q] = 0.0f;

            #pragma unroll 1
            for (int kk = 0; kk < 8; kk++) {
                const uint32_t ko = (uint32_t)kk * 32u;
                uint32_t a0[4], a1[4];
                ldsm_x4(a0, aHi0 + ko); ldsm_x4(a1, aHi1 + ko);
                #pragma unroll
                for (int jh = 0; jh < 2; jh++) {
                    uint32_t bh[4][2];
                    #pragma unroll
                    for (int j4 = 0; j4 < 4; j4++) {
                        const uint32_t bo = (uint32_t)(jh * 4 + j4) * (8u * WSTR) + ko;
                        ldsm_x2(bh[j4][0], bh[j4][1], bH + bo);
                    }
                    #pragma unroll
                    for (int j4 = 0; j4 < 4; j4++) {
                        const int j = jh * 4 + j4;
                        mma16816(acc[0][j], a0, bh[j4][0], bh[j4][1]);
                        mma16816(acc[1][j], a1, bh[j4][0], bh[j4][1]);
                    }
                }
            }

            // paired f16x2 tanh + va weighting -> e partials (32 dw rows)
            float* ep = epart + p * 528 + gm * 132;
            #pragma unroll
            for (int j = 0; j < 8; j++) {
                float2 ta = tanh2(acc[0][j][0], acc[0][j][2]);
                float2 tb = tanh2(acc[1][j][0], acc[1][j][2]);
                float2 tc2 = tanh2(acc[0][j][1], acc[0][j][3]);
                float2 td = tanh2(acc[1][j][1], acc[1][j][3]);
                float p0 = v00 * ta.x + v01 * ta.y + v10 * tb.x + v11 * tb.y;
                float p1 = v00 * tc2.x + v01 * tc2.y + v10 * td.x + v11 * td.y;
                #pragma unroll
                for (int off = 4; off <= 16; off <<= 1) {
                    p0 += __shfl_xor_sync(0xffffffffu, p0, off);
                    p1 += __shfl_xor_sync(0xffffffffu, p1, off);
                }
                if (lane < 4) {
                    ep[64 * gn + 8 * j + 2 * tc]     = p0;
                    ep[64 * gn + 8 * j + 2 * tc + 1] = p1;
                }
            }
            BAR_ARRIVE(3 + p, 512);                // e partials ready (k-loop done too)
        }
    } else {
        // ================= builder warps (8-15) =================
        const int bt = tid - 256;
        const int bw = bt >> 5;            // builder warp 0-7
        const int c  = lane;               // channel
        int* sqw = sseq + bw * 80;         // private slice [4][20]
        const float* M0 = Msh + c * 33;           // bias folded in
        const float* M1 = Msh + (32 + c) * 33;
        const float* M2 = Msh + (64 + c) * 33;
        const int nb = bw * 16;
        float ctxAcc[4] = {0.0f, 0.0f, 0.0f, 0.0f};
        float m_run = -3.4e38f, Z_run = 0.0f;

        for (int tile = 0; tile < NTILES; tile++) {
            const int p = tile & 1;
            // -- per-warp token load (no block barrier) --
            {
                const int base = tile * NT + nb;
                #pragma unroll
                for (int idx = lane; idx < 72; idx += 32) {
                    int s = idx / 18, o = idx - s * 18;
                    sqw[s * 20 + o] = seqb[s * NL + base + o];
                }
                __syncwarp();
            }
            // build H(tile) into buf p: safe — EREADY(tile-2) was synced during
            // iteration tile-1's epilogue, implying GEMM finished reading buf p.
            {
                char* hb = smem + OFF_H + p * 34816;
                int u0[4], u1[4];
                #pragma unroll
                for (int s = 0; s < 4; s++) {
                    u0[s] = sqw[s * 20];
                    u1[s] = sqw[s * 20 + 1];
                }
                #pragma unroll 2
                for (int i = 0; i < 16; i++) {
                    const int n = nb + i;
                    float v[4];
                    #pragma unroll
                    for (int s = 0; s < 4; s++) {
                        int u2 = sqw[s * 20 + i + 2];
                        v[s] = fmaxf(M0[u0[s]] + M1[u1[s]] + M2[u2], 0.0f);
                        u0[s] = u1[s]; u1[s] = u2;
                    }
                    uint32_t pk0, pk1;
                    asm("cvt.rn.f16x2.f32 %0, %1, %2;" : "=r"(pk0) : "f"(v[1]), "f"(v[0]));
                    asm("cvt.rn.f16x2.f32 %0, %1, %2;" : "=r"(pk1) : "f"(v[3]), "f"(v[2]));
                    uint2 pk = make_uint2(pk0, pk1);
                    *(uint2*)(hb + (uint32_t)n * WSTR + (uint32_t)c * 8u) = pk;
                }
            }
            BAR_ARRIVE(1 + p, 512);                // H(tile) ready

            if (tile >= 1) {
                const int pp = (tile - 1) & 1;
                BAR_SYNC(3 + pp, 512);             // e partials(tile-1) ready
                builder_epilogue(pp, bw, lane, smem, epart, m_run, Z_run, ctxAcc);
            }
        }
        // ---- tail: epilogue for tile 15 (parity 1, H buf 1) ----
        BAR_SYNC(3 + 1, 512);
        builder_epilogue(1, bw, lane, smem, epart, m_run, Z_run, ctxAcc);
        #pragma unroll
        for (int j = 0; j < 4; j++)
            ctxp[bw * 128 + lane * 4 + j] = ctxAcc[j];
        if (bw == 0 && lane == 0) scal[1] = Z_run;
    }

    __syncthreads();
    if (tid < 128) {
        float invz = 1.0f / scal[1];
        float s = 0.0f;
        #pragma unroll
        for (int q = 0; q < 8; q++) s += ctxp[q * 128 + tid];
        out[b * DD + tid] = s * invz;
    }
}

extern "C" void kernel_launch(void* const* d_in, const int* in_sizes, int n_in,
                              void* d_out, int out_size)
{
    const int*   seq   = (const int*)  d_in[0];  // [128, 8194] int32
    const float* emb   = (const float*)d_in[1];  // [26, 5]
    const float* convw = (const float*)d_in[2];  // [32, 5, 3]
    const float* convb = (const float*)d_in[3];  // [32]
    const float* Wa    = (const float*)d_in[4];  // [128, 128]
    const float* va    = (const float*)d_in[5];  // [128]
    float*       out   = (float*)d_out;          // [128, 128]

    cudaFuncSetAttribute(dingo_kernel,
                         cudaFuncAttributeMaxDynamicSharedMemorySize, SMEM_BYTES);
    dingo_kernel<<<NB, TPB, SMEM_BYTES>>>(seq, emb, convw, convb, Wa, va, out);
}

// round 14
// speedup vs baseline: 1.5711x; 1.5711x over previous
#include <cuda_runtime.h>
#include <cuda_fp16.h>
#include <cstdint>

#define TPB     512
#define NB      128
#define SEQLEN  8194
#define NL      2048
#define DD      128
#define NT      128
#define NROUNDS 8        // 2 tiles per round
#define WSTR    272      // bytes per row (136 fp16) for W and H tiles
#define HBUF    34816

// shared memory layout (bytes)
#define OFF_WHI   0        // 128*272 = 34816
#define OFF_H     34816    // 4 buffers x 34816 = 139264 (pair q*2+t2)
#define OFF_MSH   174080   // 3*32*33 f32 = 12672
#define OFF_SSEQ  186752   // 8 warps x 160 i32 = 5120
#define OFF_VASH  191872   // 128 f32 = 512
#define OFF_EPART 192384   // 2 q x 2 half x 528 f32 = 8448
#define OFF_CTXP  200832   // 8*128 f32 = 4096
#define OFF_SCAL  204928   // 32 f32 = 128
#define SMEM_BYTES 205056

// named barriers: 1+q = HREADY(512), 3+q = GDONE(512), 5+q = EREADY(512)
#define BAR_ARRIVE(id, cnt) asm volatile("bar.arrive %0, %1;" :: "r"(id), "r"(cnt) : "memory")
#define BAR_SYNC(id, cnt)   asm volatile("bar.sync %0, %1;"   :: "r"(id), "r"(cnt) : "memory")

__device__ __forceinline__ uint32_t smem_u32(const void* p) {
    uint32_t a;
    asm("{ .reg .u64 t; cvta.to.shared.u64 t, %1; cvt.u32.u64 %0, t; }" : "=r"(a) : "l"(p));
    return a;
}
__device__ __forceinline__ void ldsm_x4(uint32_t* r, uint32_t a) {
    asm volatile("ldmatrix.sync.aligned.m8n8.x4.shared.b16 {%0,%1,%2,%3}, [%4];"
                 : "=r"(r[0]), "=r"(r[1]), "=r"(r[2]), "=r"(r[3]) : "r"(a));
}
__device__ __forceinline__ void ldsm_x2(uint32_t& r0, uint32_t& r1, uint32_t a) {
    asm volatile("ldmatrix.sync.aligned.m8n8.x2.shared.b16 {%0,%1}, [%2];"
                 : "=r"(r0), "=r"(r1) : "r"(a));
}
__device__ __forceinline__ void mma16816(float* c, const uint32_t* a, uint32_t b0, uint32_t b1) {
    asm volatile("mma.sync.aligned.m16n8k16.row.col.f32.f16.f16.f32 "
                 "{%0,%1,%2,%3}, {%4,%5,%6,%7}, {%8,%9}, {%0,%1,%2,%3};"
                 : "+f"(c[0]), "+f"(c[1]), "+f"(c[2]), "+f"(c[3])
                 : "r"(a[0]), "r"(a[1]), "r"(a[2]), "r"(a[3]), "r"(b0), "r"(b1));
}
// paired tanh via MUFU.TANH on f16x2: returns {tanh(a), tanh(b)}
__device__ __forceinline__ float2 tanh2(float a, float b) {
    uint32_t d2, t2;
    asm("cvt.rn.f16x2.f32 %0, %1, %2;" : "=r"(d2) : "f"(b), "f"(a));  // lo=a, hi=b
    asm("tanh.approx.f16x2 %0, %1;" : "=r"(t2) : "r"(d2));
    __half2 h = *reinterpret_cast<__half2*>(&t2);
    return __half22float2(h);   // x = tanh(a), y = tanh(b)
}

// warp-local softmax over 256 positions (two tile halves) + online ctx update
__device__ __forceinline__ void builder_epilogue2(
    int qq, int bw, int lane, char* smem, const float* epart,
    float& m_run, float& Z_run, float* ctxAcc)
{
    float e[8], mloc = -3.4e38f;
    #pragma unroll
    for (int h = 0; h < 2; h++) {
        const float* ep = epart + qq * 1056 + h * 528;
        #pragma unroll
        for (int j = 0; j < 4; j++) {
            int n = lane + j * 32;
            e[h*4+j] = ep[n] + ep[132 + n] + ep[264 + n] + ep[396 + n];
            mloc = fmaxf(mloc, e[h*4+j]);
        }
    }
    #pragma unroll
    for (int off = 16; off; off >>= 1)
        mloc = fmaxf(mloc, __shfl_xor_sync(0xffffffffu, mloc, off));
    float m_new = fmaxf(m_run, mloc);
    float alpha = __expf(m_run - m_new);
    m_run = m_new;
    float w[8], z = 0.0f;
    #pragma unroll
    for (int j = 0; j < 8; j++) { w[j] = __expf(e[j] - m_new); z += w[j]; }
    #pragma unroll
    for (int off = 16; off; off >>= 1)
        z += __shfl_xor_sync(0xffffffffu, z, off);
    Z_run = Z_run * alpha + z;
    // ctx over both halves; warp bw owns rows n=bw*16..+16 within each half
    const int srcb = (bw & 1) * 16;
    float t0 = 0.0f, t1 = 0.0f, t2 = 0.0f, t3 = 0.0f;
    #pragma unroll
    for (int h = 0; h < 2; h++) {
        const int jj = h * 4 + (bw >> 1);
        float wq = (jj == 0) ? w[0] : (jj == 1) ? w[1] : (jj == 2) ? w[2] :
                   (jj == 3) ? w[3] : (jj == 4) ? w[4] : (jj == 5) ? w[5] :
                   (jj == 6) ? w[6] : w[7];
        const char* hb = smem + OFF_H + (qq * 2 + h) * HBUF;
        #pragma unroll 4
        for (int i = 0; i < 16; i++) {
            float wv = __shfl_sync(0xffffffffu, wq, srcb + i);
            int n = bw * 16 + i;
            uint2 hv = *(const uint2*)(hb + (uint32_t)n * WSTR + (uint32_t)lane * 8u);
            float2 f0 = __half22float2(*(__half2*)&hv.x);
            float2 f1 = __half22float2(*(__half2*)&hv.y);
            t0 += wv * f0.x; t1 += wv * f0.y; t2 += wv * f1.x; t3 += wv * f1.y;
        }
    }
    ctxAcc[0] = ctxAcc[0] * alpha + t0;
    ctxAcc[1] = ctxAcc[1] * alpha + t1;
    ctxAcc[2] = ctxAcc[2] * alpha + t2;
    ctxAcc[3] = ctxAcc[3] * alpha + t3;
}

__global__ void __launch_bounds__(TPB, 1)
dingo_kernel(const int*   __restrict__ seq,
             const float* __restrict__ emb,
             const float* __restrict__ convw,
             const float* __restrict__ convb,
             const float* __restrict__ Wa,
             const float* __restrict__ va,
             float*       __restrict__ out)
{
    extern __shared__ char smem[];
    const uint32_t sb = smem_u32(smem);
    float* Msh   = (float*)(smem + OFF_MSH);   // [3][32][33], bias folded into k=0
    int*   sseq  = (int*)  (smem + OFF_SSEQ);  // per-warp slices [8][2][4][20]
    float* vash  = (float*)(smem + OFF_VASH);
    float* epart = (float*)(smem + OFF_EPART);
    float* ctxp  = (float*)(smem + OFF_CTXP);
    float* scal  = (float*)(smem + OFF_SCAL);

    const int b    = blockIdx.x;
    const int tid  = threadIdx.x;
    const int wid  = tid >> 5;
    const int lane = tid & 31;
    const int* seqb = seq + b * SEQLEN;

    // ---- setup (all 512): W fp16 row-major [dw][e]; conv-fold tables ----
    for (int i = tid; i < DD * DD; i += TPB) {
        int dw = i >> 7, e = i & 127;
        *(__half*)(smem + OFF_WHI + dw * WSTR + e * 2) = __float2half_rn(Wa[i]);
    }
    for (int i = tid; i < 3 * 32 * 26; i += TPB) {
        int k = i / 832, r = i - k * 832;
        int c = r / 26, tt = r - c * 26;
        float acc = (k == 0) ? convb[c] : 0.0f;
        #pragma unroll
        for (int q = 0; q < 5; q++)
            acc += emb[tt * 5 + q] * convw[(c * 5 + q) * 3 + k];
        Msh[(k * 32 + c) * 33 + tt] = acc;
    }
    if (tid < 128) vash[tid] = va[tid];
    __syncthreads();

    if (tid < 256) {
        // ====== GEMM warps (0-7): two m32xn64 tiles per round ======
        const int gm = wid & 3, gn = wid >> 2;
        const uint32_t aBase = (uint32_t)(32 * gm + (lane & 15)) * WSTR
                             + (uint32_t)((lane >> 4) & 1) * 16u;
        const uint32_t aHi0 = sb + OFF_WHI + aBase;
        const uint32_t aHi1 = aHi0 + 16u * WSTR;
        const int ll = lane & 15;
        const uint32_t bBase = (uint32_t)(64 * gn + (ll & 7)) * WSTR
                             + (uint32_t)((ll >> 3) & 1) * 16u;
        const int g = lane >> 2, tc = lane & 3;
        const float v00 = vash[32 * gm + g],      v01 = vash[32 * gm + 8 + g];
        const float v10 = vash[32 * gm + 16 + g], v11 = vash[32 * gm + 24 + g];

        for (int rnd = 0; rnd < NROUNDS; rnd++) {
            const int q = rnd & 1;
            BAR_SYNC(1 + q, 512);                  // both H tiles of round ready
            #pragma unroll 1
            for (int t2 = 0; t2 < 2; t2++) {
                const uint32_t bH = sb + OFF_H + (uint32_t)(q * 2 + t2) * HBUF + bBase;
                float acc[2][8][4];
                #pragma unroll
                for (int mi = 0; mi < 2; mi++)
                    #pragma unroll
                    for (int j = 0; j < 8; j++)
                        #pragma unroll
                        for (int qq2 = 0; qq2 < 4; qq2++) acc[mi][j][qq2] = 0.0f;

                #pragma unroll 1
                for (int kk = 0; kk < 8; kk++) {
                    const uint32_t ko = (uint32_t)kk * 32u;
                    uint32_t a0[4], a1[4];
                    ldsm_x4(a0, aHi0 + ko); ldsm_x4(a1, aHi1 + ko);
                    #pragma unroll
                    for (int jh = 0; jh < 2; jh++) {
                        uint32_t bh[4][2];
                        #pragma unroll
                        for (int j4 = 0; j4 < 4; j4++) {
                            const uint32_t bo = (uint32_t)(jh * 4 + j4) * (8u * WSTR) + ko;
                            ldsm_x2(bh[j4][0], bh[j4][1], bH + bo);
                        }
                        #pragma unroll
                        for (int j4 = 0; j4 < 4; j4++) {
                            const int j = jh * 4 + j4;
                            mma16816(acc[0][j], a0, bh[j4][0], bh[j4][1]);
                            mma16816(acc[1][j], a1, bh[j4][0], bh[j4][1]);
                        }
                    }
                }
                if (t2 == 1) BAR_ARRIVE(3 + q, 512);  // done reading both H bufs

                // tanh + va weighting -> e partials (32 dw rows, half t2)
                float* ep = epart + q * 1056 + t2 * 528 + gm * 132;
                #pragma unroll
                for (int j = 0; j < 8; j++) {
                    float2 ta = tanh2(acc[0][j][0], acc[0][j][2]);
                    float2 tb = tanh2(acc[1][j][0], acc[1][j][2]);
                    float2 tc2 = tanh2(acc[0][j][1], acc[0][j][3]);
                    float2 td = tanh2(acc[1][j][1], acc[1][j][3]);
                    float p0 = v00 * ta.x + v01 * ta.y + v10 * tb.x + v11 * tb.y;
                    float p1 = v00 * tc2.x + v01 * tc2.y + v10 * td.x + v11 * td.y;
                    #pragma unroll
                    for (int off = 4; off <= 16; off <<= 1) {
                        p0 += __shfl_xor_sync(0xffffffffu, p0, off);
                        p1 += __shfl_xor_sync(0xffffffffu, p1, off);
                    }
                    if (lane < 4) {
                        ep[64 * gn + 8 * j + 2 * tc]     = p0;
                        ep[64 * gn + 8 * j + 2 * tc + 1] = p1;
                    }
                }
            }
            __threadfence_block();
            BAR_ARRIVE(5 + q, 512);                // e partials (both halves) ready
        }
    } else {
        // ================= builder warps (8-15) =================
        const int bt = tid - 256;
        const int bw = bt >> 5;            // builder warp 0-7
        const int c  = lane;               // channel
        int* sqw = sseq + bw * 160;        // private slice [2][4][20]
        const float* M0 = Msh + c * 33;           // bias folded in
        const float* M1 = Msh + (32 + c) * 33;
        const float* M2 = Msh + (64 + c) * 33;
        const int nb = bw * 16;
        float ctxAcc[4] = {0.0f, 0.0f, 0.0f, 0.0f};
        float m_run = -3.4e38f, Z_run = 0.0f;

        for (int rnd = 0; rnd < NROUNDS; rnd++) {
            const int q = rnd & 1;
            // -- per-warp token load for both tiles (no block barrier) --
            #pragma unroll
            for (int t2 = 0; t2 < 2; t2++) {
                const int base = (2 * rnd + t2) * NT + nb;
                #pragma unroll
                for (int idx = lane; idx < 72; idx += 32) {
                    int s = idx / 18, o = idx - s * 18;
                    sqw[t2 * 80 + s * 20 + o] = seqb[s * NL + base + o];
                }
            }
            __syncwarp();
            if (rnd >= 2) BAR_SYNC(3 + q, 512);    // GEMM(rnd-2) done with pair q

            // build both H tiles of this round; warp bw owns 16 n in each
            #pragma unroll 1
            for (int t2 = 0; t2 < 2; t2++) {
                char* hb = smem + OFF_H + (q * 2 + t2) * HBUF;
                const int* sq = sqw + t2 * 80;
                int u0[4], u1[4];
                #pragma unroll
                for (int s = 0; s < 4; s++) {
                    u0[s] = sq[s * 20];
                    u1[s] = sq[s * 20 + 1];
                }
                #pragma unroll 2
                for (int i = 0; i < 16; i++) {
                    const int n = nb + i;
                    float v[4];
                    #pragma unroll
                    for (int s = 0; s < 4; s++) {
                        int u2 = sq[s * 20 + i + 2];
                        v[s] = fmaxf(M0[u0[s]] + M1[u1[s]] + M2[u2], 0.0f);
                        u0[s] = u1[s]; u1[s] = u2;
                    }
                    uint32_t pk0, pk1;
                    asm("cvt.rn.f16x2.f32 %0, %1, %2;" : "=r"(pk0) : "f"(v[1]), "f"(v[0]));
                    asm("cvt.rn.f16x2.f32 %0, %1, %2;" : "=r"(pk1) : "f"(v[3]), "f"(v[2]));
                    uint2 pk = make_uint2(pk0, pk1);
                    *(uint2*)(hb + (uint32_t)n * WSTR + (uint32_t)c * 8u) = pk;
                }
            }
            __threadfence_block();
            BAR_ARRIVE(1 + q, 512);                // H pair ready

            if (rnd >= 1) {
                const int qq = (rnd - 1) & 1;
                BAR_SYNC(5 + qq, 512);             // e partials(rnd-1) ready
                builder_epilogue2(qq, bw, lane, smem, epart, m_run, Z_run, ctxAcc);
            }
        }
        // ---- tail: epilogue for round 7 (q=1) ----
        BAR_SYNC(5 + 1, 512);
        builder_epilogue2(1, bw, lane, smem, epart, m_run, Z_run, ctxAcc);
        #pragma unroll
        for (int j = 0; j < 4; j++)
            ctxp[bw * 128 + lane * 4 + j] = ctxAcc[j];
        if (bw == 0 && lane == 0) scal[1] = Z_run;
    }

    __syncthreads();
    if (tid < 128) {
        float invz = 1.0f / scal[1];
        float s = 0.0f;
        #pragma unroll
        for (int q = 0; q < 8; q++) s += ctxp[q * 128 + tid];
        out[b * DD + tid] = s * invz;
    }
}

extern "C" void kernel_launch(void* const* d_in, const int* in_sizes, int n_in,
                              void* d_out, int out_size)
{
    const int*   seq   = (const int*)  d_in[0];  // [128, 8194] int32
    const float* emb   = (const float*)d_in[1];  // [26, 5]
    const float* convw = (const float*)d_in[2];  // [32, 5, 3]
    const float* convb = (const float*)d_in[3];  // [32]
    const float* Wa    = (const float*)d_in[4];  // [128, 128]
    const float* va    = (const float*)d_in[5];  // [128]
    float*       out   = (float*)d_out;          // [128, 128]

    cudaFuncSetAttribute(dingo_kernel,
                         cudaFuncAttributeMaxDynamicSharedMemorySize, SMEM_BYTES);
    dingo_kernel<<<NB, TPB, SMEM_BYTES>>>(seq, emb, convw, convb, Wa, va, out);
}